// round 14
// baseline (speedup 1.0000x reference)
#include <cuda_runtime.h>
#include <cstdint>

#define S_DIM 1024
#define S_H   16
#define S_B   4
#define S_N   1024
#define S_P   1024
#define S_J   2048
#define S_BN  (S_B * S_N)   // 4096
#define S_BJ  (S_B * S_J)   // 8192
#define MASKV (-1.0e30f)

// ---------------- scratch ----------------
__device__ float g_xn  [S_BN * S_DIM];   // layernormed x, tf32-formatted
__device__ float g_qraw[S_BN * S_DIM];   // raw Q projection
__device__ float g_ao  [S_BN * S_DIM];   // attention out, tf32-formatted
__device__ float g_kvr [S_BJ * 128];
__device__ float g_k   [S_BJ * 64];      // normalized K, tf32-formatted
__device__ float g_v   [S_BJ * 64];      // V, tf32-formatted

// ---------------- helpers ----------------
__device__ __forceinline__ uint32_t f2tf(float x) {
    uint32_t u; asm("cvt.rna.tf32.f32 %0, %1;" : "=r"(u) : "f"(x)); return u;
}
__device__ __forceinline__ float f2tf_f(float x) { return __uint_as_float(f2tf(x)); }

__device__ __forceinline__ void mma8(float* d, const uint32_t* a, const uint32_t* b) {
    asm volatile(
        "mma.sync.aligned.m16n8k8.row.col.f32.tf32.tf32.f32 "
        "{%0,%1,%2,%3}, {%4,%5,%6,%7}, {%8,%9}, {%0,%1,%2,%3};"
        : "+f"(d[0]), "+f"(d[1]), "+f"(d[2]), "+f"(d[3])
        : "r"(a[0]), "r"(a[1]), "r"(a[2]), "r"(a[3]), "r"(b[0]), "r"(b[1]));
}
__device__ __forceinline__ void cpa16(uint32_t dst, const float* src) {
    asm volatile("cp.async.cg.shared.global [%0], [%1], 16;" :: "r"(dst), "l"(src));
}
#define CP_COMMIT asm volatile("cp.async.commit_group;")
#define CP_WAIT1  asm volatile("cp.async.wait_group 1;")
#define CP_WAIT0  asm volatile("cp.async.wait_group 0;")

// ---------------- LayerNorm (emits tf32-formatted f32) ----------------
__global__ void __launch_bounds__(256) ln_kernel(const float* __restrict__ x,
                                                 const float* __restrict__ gamma,
                                                 float* __restrict__ xn) {
    int row = blockIdx.x, t = threadIdx.x;
    float4 v = ((const float4*)(x + (size_t)row * S_DIM))[t];
    float s  = v.x + v.y + v.z + v.w;
    float sq = v.x * v.x + v.y * v.y + v.z * v.z + v.w * v.w;
    __shared__ float red[16]; __shared__ float bc[2];
#pragma unroll
    for (int o = 16; o > 0; o >>= 1) {
        s  += __shfl_xor_sync(~0u, s,  o);
        sq += __shfl_xor_sync(~0u, sq, o);
    }
    if ((t & 31) == 0) { red[t >> 5] = s; red[(t >> 5) + 8] = sq; }
    __syncthreads();
    if (t == 0) {
        float ts = 0.f, tq = 0.f;
#pragma unroll
        for (int w = 0; w < 8; w++) { ts += red[w]; tq += red[w + 8]; }
        float mu = ts * (1.f / 1024.f);
        bc[0] = mu; bc[1] = rsqrtf(tq * (1.f / 1024.f) - mu * mu + 1e-5f);
    }
    __syncthreads();
    float mu = bc[0], r = bc[1];
    float4 g = ((const float4*)gamma)[t];
    float4 o = make_float4(f2tf_f((v.x - mu) * r * g.x), f2tf_f((v.y - mu) * r * g.y),
                           f2tf_f((v.z - mu) * r * g.z), f2tf_f((v.w - mu) * r * g.w));
    ((float4*)(xn + (size_t)row * S_DIM))[t] = o;
}

// ---------------- single-pass tf32 GEMM (round-12 proven: 128x128x32) ------
#define MP 44
#define MM_SMEM_BYTES (2 * 2 * 128 * MP * 4)   // 90112

template <bool CONCAT, bool ATF>
__global__ void __launch_bounds__(256) mm_tf32(const float* __restrict__ A,
                                               const float* __restrict__ A2,
                                               const float* __restrict__ B,
                                               float* __restrict__ C,
                                               int M, int N, int K) {
    extern __shared__ float sh[];
    float* As = sh;
    float* Bs = sh + 2 * 128 * MP;
    const int t = threadIdx.x;
    const int m0 = blockIdx.y * 128, n0 = blockIdx.x * 128;
    const int lane = t & 31, g = lane >> 2, c = lane & 3;
    const int wm = (t >> 5) & 1, wn = t >> 6;

    const float* asrc[4]; const float* bsrc[4];
    int aoff[4], boff[4];
#pragma unroll
    for (int i = 0; i < 4; i++) {
        int f = t + 256 * i;
        int row = f >> 3, c4 = (f & 7) << 2;
        int gm = m0 + row;
        const float* ap;
        if (CONCAT) {
            int bb = gm >> 11, s = gm & 2047;
            ap = (s < S_P) ? (A  + ((size_t)bb * S_P + s) * S_DIM)
                           : (A2 + ((size_t)bb * S_N + (s - S_P)) * S_DIM);
        } else ap = A + (size_t)gm * K;
        asrc[i] = ap + c4;                          aoff[i] = row * MP + c4;
        bsrc[i] = B + (size_t)(n0 + row) * K + c4;  boff[i] = row * MP + c4;
    }
    uint32_t aB = (uint32_t)__cvta_generic_to_shared(As);
    uint32_t bB = (uint32_t)__cvta_generic_to_shared(Bs);

    float acc[4][4][4];
#pragma unroll
    for (int mt = 0; mt < 4; mt++)
#pragma unroll
        for (int nt = 0; nt < 4; nt++)
#pragma unroll
            for (int i = 0; i < 4; i++) acc[mt][nt][i] = 0.f;

    const int CH = K >> 5;
#pragma unroll
    for (int i = 0; i < 4; i++) { cpa16(aB + 4 * aoff[i], asrc[i]); cpa16(bB + 4 * boff[i], bsrc[i]); }
    CP_COMMIT;

    for (int ch = 0; ch < CH; ch++) {
        int st = ch & 1;
        if (ch + 1 < CH) {
            int st2 = (ch + 1) & 1, ko = (ch + 1) << 5;
            uint32_t a2 = aB + 4 * st2 * 128 * MP, b2 = bB + 4 * st2 * 128 * MP;
#pragma unroll
            for (int i = 0; i < 4; i++) { cpa16(a2 + 4 * aoff[i], asrc[i] + ko); cpa16(b2 + 4 * boff[i], bsrc[i] + ko); }
            CP_COMMIT; CP_WAIT1;
        } else CP_WAIT0;
        __syncthreads();

        const float* as = As + st * 128 * MP;
        const float* bs = Bs + st * 128 * MP;
#pragma unroll
        for (int ks = 0; ks < 4; ks++) {
            int col = ks * 8 + c;
            uint32_t af[4][4], bf[4][2];
#pragma unroll
            for (int mt = 0; mt < 4; mt++) {
                int r0 = wm * 64 + mt * 16 + g;
                if (ATF) {
                    af[mt][0] = __float_as_uint(as[r0 * MP + col]);
                    af[mt][1] = __float_as_uint(as[(r0 + 8) * MP + col]);
                    af[mt][2] = __float_as_uint(as[r0 * MP + col + 4]);
                    af[mt][3] = __float_as_uint(as[(r0 + 8) * MP + col + 4]);
                } else {
                    af[mt][0] = f2tf(as[r0 * MP + col]);
                    af[mt][1] = f2tf(as[(r0 + 8) * MP + col]);
                    af[mt][2] = f2tf(as[r0 * MP + col + 4]);
                    af[mt][3] = f2tf(as[(r0 + 8) * MP + col + 4]);
                }
            }
#pragma unroll
            for (int nt = 0; nt < 4; nt++) {
                int rb = wn * 32 + nt * 8 + g;
                bf[nt][0] = f2tf(bs[rb * MP + col]);
                bf[nt][1] = f2tf(bs[rb * MP + col + 4]);
            }
#pragma unroll
            for (int mt = 0; mt < 4; mt++)
#pragma unroll
                for (int nt = 0; nt < 4; nt++)
                    mma8(acc[mt][nt], af[mt], bf[nt]);
        }
        __syncthreads();
    }
#pragma unroll
    for (int mt = 0; mt < 4; mt++) {
        int r0 = m0 + wm * 64 + mt * 16 + g;
#pragma unroll
        for (int nt = 0; nt < 4; nt++) {
            int col = n0 + wn * 32 + nt * 8 + 2 * c;
            *(float2*)&C[(size_t)r0 * N + col]       = make_float2(acc[mt][nt][0], acc[mt][nt][1]);
            *(float2*)&C[(size_t)(r0 + 8) * N + col] = make_float2(acc[mt][nt][2], acc[mt][nt][3]);
        }
    }
}

// ---------------- KV norm/split (emits tf32-formatted) ----------------
__global__ void __launch_bounds__(256) kvnorm_kernel(const float* __restrict__ kvraw,
                                                     const float* __restrict__ kscale,
                                                     float* __restrict__ k,
                                                     float* __restrict__ v) {
    int t = threadIdx.x, r = blockIdx.x * 8 + (t >> 5), lane = t & 31;
    const float* src = kvraw + (size_t)r * 128;
    float a0 = src[lane], a1 = src[lane + 32];
    float ss = a0 * a0 + a1 * a1;
#pragma unroll
    for (int o = 16; o > 0; o >>= 1) ss += __shfl_xor_sync(~0u, ss, o);
    float inv = 1.f / fmaxf(sqrtf(ss), 1e-12f);
    k[(size_t)r * 64 + lane]      = f2tf_f(a0 * inv * kscale[lane]);
    k[(size_t)r * 64 + lane + 32] = f2tf_f(a1 * inv * kscale[lane + 32]);
    v[(size_t)r * 64 + lane]      = f2tf_f(src[64 + lane]);
    v[(size_t)r * 64 + lane + 32] = f2tf_f(src[96 + lane]);
}

// ---------------- tensor-core attention: 128-row Q tiles, 8 warps ----------
// Warp w owns query rows i0+16w..+15 (i0 = qt2*128). K/V tiles stay 64 rows;
// each staging+sync now feeds 8 warps (2x mma per tile, 43% fewer tiles).
// Q staged per-warp into its own P pad (warp-local). Warps fully outside a
// tile's band/causal region branch around the whole tile body (warp-uniform).
#define KP 76
#define VP 72
#define PQ 76
#define ATTN_SMEM_FLOATS (64 * KP + 64 * VP + 8 * 16 * PQ + 192)
#define ATTN_SMEM_BYTES  (ATTN_SMEM_FLOATS * 4)   // 77568

__global__ void __launch_bounds__(256) attn_tc(const float* __restrict__ qraw,
                                               const float* __restrict__ k,
                                               const float* __restrict__ v,
                                               const float* __restrict__ bias,
                                               const float* __restrict__ qscale,
                                               float* __restrict__ ao) {
    extern __shared__ float sm[];
    float* Ks  = sm;                                   // [64][KP]
    float* Vs  = sm + 64 * KP;                         // [64][VP]
    float* Pp  = sm + 64 * KP + 64 * VP;               // [8][16][PQ]
    float* nrm = sm + 64 * KP + 64 * VP + 8 * 16 * PQ; // [128]
    float* qss = nrm + 128;                            // [64]
    int qt2 = blockIdx.x, bh = blockIdx.y, b = bh >> 4, h = bh & 15;
    int i0 = qt2 << 7;
    int t = threadIdx.x, w = t >> 5, lane = t & 31, g = lane >> 2, c = lane & 3;
    float* Pw = Pp + w * 16 * PQ;
    const int R0 = i0 + w * 16;

    // ---- per-warp Q staging into own P pad (16 rows x 64 cols) ----
    const float* qb = qraw + ((size_t)(b * S_N + R0)) * S_DIM + h * 64;
#pragma unroll
    for (int i = 0; i < 8; i++) {
        int fi = i * 32 + lane;
        int r = fi >> 4, d4 = (fi & 15) << 2;
        *(float4*)&Pw[r * PQ + d4] = *(const float4*)(qb + (size_t)r * S_DIM + d4);
    }
    if (t < 64) qss[t] = qscale[t];
    __syncthreads();   // qss visible (Pw is warp-local)

    // warp-local row l2 norms: 2 lanes per row, 16 rows
    {
        int row = lane >> 1, half = lane & 1;
        const float* rp = Pw + row * PQ + half * 32;
        float ss = 0.f;
#pragma unroll
        for (int i = 0; i < 8; i++) {
            float4 x = *(const float4*)(rp + i * 4);
            ss += x.x * x.x + x.y * x.y + x.z * x.z + x.w * x.w;
        }
        ss += __shfl_xor_sync(~0u, ss, 1);
        if (half == 0) nrm[w * 16 + row] = 1.f / fmaxf(sqrtf(ss), 1e-12f);
    }
    __syncwarp();
    uint32_t qf[8][4];
    {
        float inv_lo = nrm[w * 16 + g], inv_hi = nrm[w * 16 + g + 8];
        int rlo = g * PQ, rhi = (g + 8) * PQ;
#pragma unroll
        for (int kc = 0; kc < 8; kc++) {
            int col = kc * 8 + c;
            float s0 = qss[col], s4 = qss[col + 4];
            qf[kc][0] = f2tf(Pw[rlo + col] * inv_lo * s0);
            qf[kc][1] = f2tf(Pw[rhi + col] * inv_hi * s0);
            qf[kc][2] = f2tf(Pw[rlo + col + 4] * inv_lo * s4);
            qf[kc][3] = f2tf(Pw[rhi + col + 4] * inv_hi * s4);
        }
    }

    float m_lo = MASKV, m_hi = MASKV, l_lo = 0.f, l_hi = 0.f;
    float oacc[8][4];
#pragma unroll
    for (int nt = 0; nt < 8; nt++)
#pragma unroll
        for (int i = 0; i < 4; i++) oacc[nt][i] = 0.f;

    const int iq_lo = R0 + g, iq_hi = iq_lo + 8;
    int nPre = qt2 ? 3 : 2;
    int nTiles = nPre + 2 * qt2 + 2;

    for (int tix = 0; tix < nTiles; tix++) {
        int isPre = (tix < nPre);
        int cbase = isPre ? ((qt2 ? (2 * qt2 - 1 + tix) : tix) << 6)
                          : ((tix - nPre) << 6);
        int kvrow0 = (isPre ? 0 : S_P) + cbase;

        // stage K,V (256 threads, 4 float4 each)
        const float* kb = k + ((size_t)b * S_J + kvrow0) * 64;
        const float* vb = v + ((size_t)b * S_J + kvrow0) * 64;
        for (int f = t; f < 1024; f += 256) {
            int r = f >> 4, d4 = (f & 15) << 2;
            *(float4*)&Ks[r * KP + d4] = *(const float4*)(kb + (size_t)r * 64 + d4);
            *(float4*)&Vs[r * VP + d4] = *(const float4*)(vb + (size_t)r * 64 + d4);
        }
        __syncthreads();

        // warp-uniform whole-tile activity test (skipped tile == all-MASKV tile)
        bool active = isPre ? (cbase <= R0 + 15 && cbase + 63 >= R0 - 15)
                            : (cbase <= R0 + 15);
        if (active) {
            float sacc[8][4];
#pragma unroll
            for (int nt = 0; nt < 8; nt++)
#pragma unroll
                for (int i = 0; i < 4; i++) sacc[nt][i] = 0.f;
#pragma unroll
            for (int kc = 0; kc < 8; kc++) {
                int col = kc * 8 + c;
#pragma unroll
                for (int nt = 0; nt < 8; nt++) {
                    uint32_t bb[2];
                    int rb = (nt * 8 + g) * KP;
                    bb[0] = __float_as_uint(Ks[rb + col]);
                    bb[1] = __float_as_uint(Ks[rb + col + 4]);
                    mma8(sacc[nt], qf[kc], bb);
                }
            }
#pragma unroll
            for (int nt = 0; nt < 8; nt++) {
                int jc = cbase + nt * 8 + 2 * c;
                if (isPre) {
                    sacc[nt][0] = (iq_lo >= jc     && iq_lo - jc < 16)     ? sacc[nt][0] * 8.f : MASKV;
                    sacc[nt][1] = (iq_lo >= jc + 1 && iq_lo - jc - 1 < 16) ? sacc[nt][1] * 8.f : MASKV;
                    sacc[nt][2] = (iq_hi >= jc     && iq_hi - jc < 16)     ? sacc[nt][2] * 8.f : MASKV;
                    sacc[nt][3] = (iq_hi >= jc + 1 && iq_hi - jc - 1 < 16) ? sacc[nt][3] * 8.f : MASKV;
                } else {
                    float2 blo = *(const float2*)(bias + ((size_t)h * S_N + iq_lo) * S_N + jc);
                    float2 bhi = *(const float2*)(bias + ((size_t)h * S_N + iq_hi) * S_N + jc);
                    sacc[nt][0] = (jc     <= iq_lo) ? sacc[nt][0] * 8.f + blo.x : MASKV;
                    sacc[nt][1] = (jc + 1 <= iq_lo) ? sacc[nt][1] * 8.f + blo.y : MASKV;
                    sacc[nt][2] = (jc     <= iq_hi) ? sacc[nt][2] * 8.f + bhi.x : MASKV;
                    sacc[nt][3] = (jc + 1 <= iq_hi) ? sacc[nt][3] * 8.f + bhi.y : MASKV;
                }
            }
            float mx_lo = MASKV, mx_hi = MASKV;
#pragma unroll
            for (int nt = 0; nt < 8; nt++) {
                mx_lo = fmaxf(mx_lo, fmaxf(sacc[nt][0], sacc[nt][1]));
                mx_hi = fmaxf(mx_hi, fmaxf(sacc[nt][2], sacc[nt][3]));
            }
            mx_lo = fmaxf(mx_lo, __shfl_xor_sync(~0u, mx_lo, 1));
            mx_lo = fmaxf(mx_lo, __shfl_xor_sync(~0u, mx_lo, 2));
            mx_hi = fmaxf(mx_hi, __shfl_xor_sync(~0u, mx_hi, 1));
            mx_hi = fmaxf(mx_hi, __shfl_xor_sync(~0u, mx_hi, 2));
            float mn_lo = fmaxf(m_lo, mx_lo), mn_hi = fmaxf(m_hi, mx_hi);
            float r_lo = __expf(m_lo - mn_lo), r_hi = __expf(m_hi - mn_hi);
            float ps_lo = 0.f, ps_hi = 0.f;
#pragma unroll
            for (int nt = 0; nt < 8; nt++) {
                float p0 = (sacc[nt][0] > -1e29f) ? __expf(sacc[nt][0] - mn_lo) : 0.f;
                float p1 = (sacc[nt][1] > -1e29f) ? __expf(sacc[nt][1] - mn_lo) : 0.f;
                float p2 = (sacc[nt][2] > -1e29f) ? __expf(sacc[nt][2] - mn_hi) : 0.f;
                float p3 = (sacc[nt][3] > -1e29f) ? __expf(sacc[nt][3] - mn_hi) : 0.f;
                ps_lo += p0 + p1; ps_hi += p2 + p3;
                int col = nt * 8 + 2 * c;
                *(float2*)&Pw[g * PQ + col]       = make_float2(f2tf_f(p0), f2tf_f(p1));
                *(float2*)&Pw[(g + 8) * PQ + col] = make_float2(f2tf_f(p2), f2tf_f(p3));
            }
            ps_lo += __shfl_xor_sync(~0u, ps_lo, 1);
            ps_lo += __shfl_xor_sync(~0u, ps_lo, 2);
            ps_hi += __shfl_xor_sync(~0u, ps_hi, 1);
            ps_hi += __shfl_xor_sync(~0u, ps_hi, 2);
            l_lo = l_lo * r_lo + ps_lo; l_hi = l_hi * r_hi + ps_hi;
            m_lo = mn_lo; m_hi = mn_hi;
#pragma unroll
            for (int nt = 0; nt < 8; nt++) {
                oacc[nt][0] *= r_lo; oacc[nt][1] *= r_lo;
                oacc[nt][2] *= r_hi; oacc[nt][3] *= r_hi;
            }
            __syncwarp();
#pragma unroll
            for (int kc = 0; kc < 8; kc++) {
                uint32_t pa[4];
                int col = kc * 8 + c;
                pa[0] = __float_as_uint(Pw[g * PQ + col]);
                pa[1] = __float_as_uint(Pw[(g + 8) * PQ + col]);
                pa[2] = __float_as_uint(Pw[g * PQ + col + 4]);
                pa[3] = __float_as_uint(Pw[(g + 8) * PQ + col + 4]);
#pragma unroll
                for (int nt = 0; nt < 8; nt++) {
                    uint32_t bb[2];
                    bb[0] = __float_as_uint(Vs[(kc * 8 + c) * VP + nt * 8 + g]);
                    bb[1] = __float_as_uint(Vs[(kc * 8 + c + 4) * VP + nt * 8 + g]);
                    mma8(oacc[nt], pa, bb);
                }
            }
        }
        __syncthreads();
    }

    float li_lo = 1.f / l_lo, li_hi = 1.f / l_hi;
    float* orow_lo = ao + ((size_t)(b * S_N + iq_lo)) * S_DIM + h * 64;
    float* orow_hi = ao + ((size_t)(b * S_N + iq_hi)) * S_DIM + h * 64;
#pragma unroll
    for (int nt = 0; nt < 8; nt++) {
        int col = nt * 8 + 2 * c;
        *(float2*)(orow_lo + col) = make_float2(f2tf_f(oacc[nt][0] * li_lo), f2tf_f(oacc[nt][1] * li_lo));
        *(float2*)(orow_hi + col) = make_float2(f2tf_f(oacc[nt][2] * li_hi), f2tf_f(oacc[nt][3] * li_hi));
    }
}

// ---------------- launch (fork/join: KV chain overlaps LN+QGEMM) -----------
extern "C" void kernel_launch(void* const* d_in, const int* in_sizes, int n_in,
                              void* d_out, int out_size) {
    const float* x      = (const float*)d_in[0];
    const float* prefix = (const float*)d_in[1];
    const float* bias   = (const float*)d_in[2];
    const float* gamma  = (const float*)d_in[3];
    const float* Wq     = (const float*)d_in[4];
    const float* Wkv    = (const float*)d_in[5];
    const float* qscale = (const float*)d_in[6];
    const float* kscale = (const float*)d_in[7];
    const float* Wo     = (const float*)d_in[8];
    float* out = (float*)d_out;

    float *xn, *qraw, *aob, *kvraw, *kk, *vv;
    cudaGetSymbolAddress((void**)&xn,    g_xn);
    cudaGetSymbolAddress((void**)&qraw,  g_qraw);
    cudaGetSymbolAddress((void**)&aob,   g_ao);
    cudaGetSymbolAddress((void**)&kvraw, g_kvr);
    cudaGetSymbolAddress((void**)&kk,    g_k);
    cudaGetSymbolAddress((void**)&vv,    g_v);

    static cudaStream_t s2 = nullptr;
    static cudaEvent_t evRoot = nullptr, evKV = nullptr;
    if (s2 == nullptr) {
        cudaStreamCreateWithFlags(&s2, cudaStreamNonBlocking);
        cudaEventCreateWithFlags(&evRoot, cudaEventDisableTiming);
        cudaEventCreateWithFlags(&evKV,   cudaEventDisableTiming);
        cudaFuncSetAttribute(mm_tf32<false, true>,  cudaFuncAttributeMaxDynamicSharedMemorySize, MM_SMEM_BYTES);
        cudaFuncSetAttribute(mm_tf32<true,  false>, cudaFuncAttributeMaxDynamicSharedMemorySize, MM_SMEM_BYTES);
        cudaFuncSetAttribute(attn_tc, cudaFuncAttributeMaxDynamicSharedMemorySize, ATTN_SMEM_BYTES);
    }

    // fork
    cudaEventRecord(evRoot, 0);
    cudaStreamWaitEvent(s2, evRoot, 0);

    // branch B (s2): KV chain — independent of LayerNorm/QGEMM
    mm_tf32<true, false><<<dim3(1, 64), 256, MM_SMEM_BYTES, s2>>>(prefix, x, Wkv, kvraw, S_BJ, 128, S_DIM);
    kvnorm_kernel<<<S_BJ / 8, 256, 0, s2>>>(kvraw, kscale, kk, vv);
    cudaEventRecord(evKV, s2);

    // branch A (origin stream): LN -> QGEMM
    ln_kernel<<<S_BN, 256>>>(x, gamma, xn);
    mm_tf32<false, true><<<dim3(8, 32), 256, MM_SMEM_BYTES>>>(xn, nullptr, Wq, qraw, S_BN, S_DIM, S_DIM);

    // join
    cudaStreamWaitEvent(0, evKV, 0);
    attn_tc<<<dim3(8, 64), 256, ATTN_SMEM_BYTES>>>(qraw, kk, vv, bias, qscale, aob);
    // out = attn_out @ Wo^T
    mm_tf32<false, true><<<dim3(8, 32), 256, MM_SMEM_BYTES>>>(aob, nullptr, Wo, out, S_BN, S_DIM, S_DIM);
}

// round 15
// speedup vs baseline: 1.2851x; 1.2851x over previous
#include <cuda_runtime.h>
#include <cstdint>

#define S_DIM 1024
#define S_H   16
#define S_B   4
#define S_N   1024
#define S_P   1024
#define S_J   2048
#define S_BN  (S_B * S_N)   // 4096
#define S_BJ  (S_B * S_J)   // 8192
#define MASKV (-1.0e30f)

// ---------------- scratch ----------------
__device__ float g_xn  [S_BN * S_DIM];   // layernormed x, tf32-formatted
__device__ float g_qraw[S_BN * S_DIM];   // raw Q projection
__device__ float g_ao  [S_BN * S_DIM];   // attention out, tf32-formatted
__device__ float g_kvr [S_BJ * 128];
__device__ float g_k   [S_BJ * 64];      // normalized K, tf32-formatted
__device__ float g_v   [S_BJ * 64];      // V, tf32-formatted

// ---------------- helpers ----------------
__device__ __forceinline__ uint32_t f2tf(float x) {
    uint32_t u; asm("cvt.rna.tf32.f32 %0, %1;" : "=r"(u) : "f"(x)); return u;
}
__device__ __forceinline__ float f2tf_f(float x) { return __uint_as_float(f2tf(x)); }

__device__ __forceinline__ void mma8(float* d, const uint32_t* a, const uint32_t* b) {
    asm volatile(
        "mma.sync.aligned.m16n8k8.row.col.f32.tf32.tf32.f32 "
        "{%0,%1,%2,%3}, {%4,%5,%6,%7}, {%8,%9}, {%0,%1,%2,%3};"
        : "+f"(d[0]), "+f"(d[1]), "+f"(d[2]), "+f"(d[3])
        : "r"(a[0]), "r"(a[1]), "r"(a[2]), "r"(a[3]), "r"(b[0]), "r"(b[1]));
}
__device__ __forceinline__ void cpa16(uint32_t dst, const float* src) {
    asm volatile("cp.async.cg.shared.global [%0], [%1], 16;" :: "r"(dst), "l"(src));
}
#define CP_COMMIT asm volatile("cp.async.commit_group;")
#define CP_WAIT1  asm volatile("cp.async.wait_group 1;")
#define CP_WAIT0  asm volatile("cp.async.wait_group 0;")

// ---------------- LayerNorm (emits tf32-formatted f32) ----------------
__global__ void __launch_bounds__(256) ln_kernel(const float* __restrict__ x,
                                                 const float* __restrict__ gamma,
                                                 float* __restrict__ xn) {
    int row = blockIdx.x, t = threadIdx.x;
    float4 v = ((const float4*)(x + (size_t)row * S_DIM))[t];
    float s  = v.x + v.y + v.z + v.w;
    float sq = v.x * v.x + v.y * v.y + v.z * v.z + v.w * v.w;
    __shared__ float red[16]; __shared__ float bc[2];
#pragma unroll
    for (int o = 16; o > 0; o >>= 1) {
        s  += __shfl_xor_sync(~0u, s,  o);
        sq += __shfl_xor_sync(~0u, sq, o);
    }
    if ((t & 31) == 0) { red[t >> 5] = s; red[(t >> 5) + 8] = sq; }
    __syncthreads();
    if (t == 0) {
        float ts = 0.f, tq = 0.f;
#pragma unroll
        for (int w = 0; w < 8; w++) { ts += red[w]; tq += red[w + 8]; }
        float mu = ts * (1.f / 1024.f);
        bc[0] = mu; bc[1] = rsqrtf(tq * (1.f / 1024.f) - mu * mu + 1e-5f);
    }
    __syncthreads();
    float mu = bc[0], r = bc[1];
    float4 g = ((const float4*)gamma)[t];
    float4 o = make_float4(f2tf_f((v.x - mu) * r * g.x), f2tf_f((v.y - mu) * r * g.y),
                           f2tf_f((v.z - mu) * r * g.z), f2tf_f((v.w - mu) * r * g.w));
    ((float4*)(xn + (size_t)row * S_DIM))[t] = o;
}

// ---------------- single-pass tf32 GEMM (round-12 proven: 128x128x32) ------
#define MP 44
#define MM_SMEM_BYTES (2 * 2 * 128 * MP * 4)   // 90112

template <bool CONCAT, bool ATF>
__global__ void __launch_bounds__(256) mm_tf32(const float* __restrict__ A,
                                               const float* __restrict__ A2,
                                               const float* __restrict__ B,
                                               float* __restrict__ C,
                                               int M, int N, int K) {
    extern __shared__ float sh[];
    float* As = sh;
    float* Bs = sh + 2 * 128 * MP;
    const int t = threadIdx.x;
    const int m0 = blockIdx.y * 128, n0 = blockIdx.x * 128;
    const int lane = t & 31, g = lane >> 2, c = lane & 3;
    const int wm = (t >> 5) & 1, wn = t >> 6;

    const float* asrc[4]; const float* bsrc[4];
    int aoff[4], boff[4];
#pragma unroll
    for (int i = 0; i < 4; i++) {
        int f = t + 256 * i;
        int row = f >> 3, c4 = (f & 7) << 2;
        int gm = m0 + row;
        const float* ap;
        if (CONCAT) {
            int bb = gm >> 11, s = gm & 2047;
            ap = (s < S_P) ? (A  + ((size_t)bb * S_P + s) * S_DIM)
                           : (A2 + ((size_t)bb * S_N + (s - S_P)) * S_DIM);
        } else ap = A + (size_t)gm * K;
        asrc[i] = ap + c4;                          aoff[i] = row * MP + c4;
        bsrc[i] = B + (size_t)(n0 + row) * K + c4;  boff[i] = row * MP + c4;
    }
    uint32_t aB = (uint32_t)__cvta_generic_to_shared(As);
    uint32_t bB = (uint32_t)__cvta_generic_to_shared(Bs);

    float acc[4][4][4];
#pragma unroll
    for (int mt = 0; mt < 4; mt++)
#pragma unroll
        for (int nt = 0; nt < 4; nt++)
#pragma unroll
            for (int i = 0; i < 4; i++) acc[mt][nt][i] = 0.f;

    const int CH = K >> 5;
#pragma unroll
    for (int i = 0; i < 4; i++) { cpa16(aB + 4 * aoff[i], asrc[i]); cpa16(bB + 4 * boff[i], bsrc[i]); }
    CP_COMMIT;

    for (int ch = 0; ch < CH; ch++) {
        int st = ch & 1;
        if (ch + 1 < CH) {
            int st2 = (ch + 1) & 1, ko = (ch + 1) << 5;
            uint32_t a2 = aB + 4 * st2 * 128 * MP, b2 = bB + 4 * st2 * 128 * MP;
#pragma unroll
            for (int i = 0; i < 4; i++) { cpa16(a2 + 4 * aoff[i], asrc[i] + ko); cpa16(b2 + 4 * boff[i], bsrc[i] + ko); }
            CP_COMMIT; CP_WAIT1;
        } else CP_WAIT0;
        __syncthreads();

        const float* as = As + st * 128 * MP;
        const float* bs = Bs + st * 128 * MP;
#pragma unroll
        for (int ks = 0; ks < 4; ks++) {
            int col = ks * 8 + c;
            uint32_t af[4][4], bf[4][2];
#pragma unroll
            for (int mt = 0; mt < 4; mt++) {
                int r0 = wm * 64 + mt * 16 + g;
                if (ATF) {
                    af[mt][0] = __float_as_uint(as[r0 * MP + col]);
                    af[mt][1] = __float_as_uint(as[(r0 + 8) * MP + col]);
                    af[mt][2] = __float_as_uint(as[r0 * MP + col + 4]);
                    af[mt][3] = __float_as_uint(as[(r0 + 8) * MP + col + 4]);
                } else {
                    af[mt][0] = f2tf(as[r0 * MP + col]);
                    af[mt][1] = f2tf(as[(r0 + 8) * MP + col]);
                    af[mt][2] = f2tf(as[r0 * MP + col + 4]);
                    af[mt][3] = f2tf(as[(r0 + 8) * MP + col + 4]);
                }
            }
#pragma unroll
            for (int nt = 0; nt < 4; nt++) {
                int rb = wn * 32 + nt * 8 + g;
                bf[nt][0] = f2tf(bs[rb * MP + col]);
                bf[nt][1] = f2tf(bs[rb * MP + col + 4]);
            }
#pragma unroll
            for (int mt = 0; mt < 4; mt++)
#pragma unroll
                for (int nt = 0; nt < 4; nt++)
                    mma8(acc[mt][nt], af[mt], bf[nt]);
        }
        __syncthreads();
    }
#pragma unroll
    for (int mt = 0; mt < 4; mt++) {
        int r0 = m0 + wm * 64 + mt * 16 + g;
#pragma unroll
        for (int nt = 0; nt < 4; nt++) {
            int col = n0 + wn * 32 + nt * 8 + 2 * c;
            *(float2*)&C[(size_t)r0 * N + col]       = make_float2(acc[mt][nt][0], acc[mt][nt][1]);
            *(float2*)&C[(size_t)(r0 + 8) * N + col] = make_float2(acc[mt][nt][2], acc[mt][nt][3]);
        }
    }
}

// ---------------- KV norm/split (emits tf32-formatted) ----------------
__global__ void __launch_bounds__(256) kvnorm_kernel(const float* __restrict__ kvraw,
                                                     const float* __restrict__ kscale,
                                                     float* __restrict__ k,
                                                     float* __restrict__ v) {
    int t = threadIdx.x, r = blockIdx.x * 8 + (t >> 5), lane = t & 31;
    const float* src = kvraw + (size_t)r * 128;
    float a0 = src[lane], a1 = src[lane + 32];
    float ss = a0 * a0 + a1 * a1;
#pragma unroll
    for (int o = 16; o > 0; o >>= 1) ss += __shfl_xor_sync(~0u, ss, o);
    float inv = 1.f / fmaxf(sqrtf(ss), 1e-12f);
    k[(size_t)r * 64 + lane]      = f2tf_f(a0 * inv * kscale[lane]);
    k[(size_t)r * 64 + lane + 32] = f2tf_f(a1 * inv * kscale[lane + 32]);
    v[(size_t)r * 64 + lane]      = f2tf_f(src[64 + lane]);
    v[(size_t)r * 64 + lane + 32] = f2tf_f(src[96 + lane]);
}

// ---------------- tensor-core attention (round-10/12 proven) ---------------
// Pointers are pre-offset by the launch for batch halves; bh = blockIdx.y is
// relative within the half (b = bh>>4 in {0,1}).
#define KP 76
#define VP 72
#define PQ 76
#define ATTN_SMEM_FLOATS (64 * KP + 64 * VP + 64 * PQ + 128)
#define ATTN_SMEM_BYTES  (ATTN_SMEM_FLOATS * 4)   // 57856

__global__ void __launch_bounds__(128) attn_tc(const float* __restrict__ qraw,
                                               const float* __restrict__ k,
                                               const float* __restrict__ v,
                                               const float* __restrict__ bias,
                                               const float* __restrict__ qscale,
                                               float* __restrict__ ao) {
    extern __shared__ float sm[];
    float* Ks  = sm;
    float* Vs  = sm + 64 * KP;
    float* Pp  = sm + 64 * KP + 64 * VP;
    float* nrm = sm + 64 * KP + 64 * VP + 64 * PQ;   // [64]
    float* qss = nrm + 64;                            // [64]
    int qt = blockIdx.x, bh = blockIdx.y, b = bh >> 4, h = bh & 15;
    int i0 = qt << 6;
    int t = threadIdx.x, w = t >> 5, lane = t & 31, g = lane >> 2, c = lane & 3;
    float* Pw = Pp + w * 16 * PQ;

    const float* qbase = qraw + ((size_t)(b * S_N + i0)) * S_DIM + h * 64;
    for (int f = t; f < 1024; f += 128) {
        int r = f >> 4, d4 = (f & 15) << 2;
        *(float4*)&Ks[r * KP + d4] = *(const float4*)(qbase + (size_t)r * S_DIM + d4);
    }
    if (t < 64) qss[t] = qscale[t];
    __syncthreads();
    {
        int row = t >> 1, half = t & 1;
        const float* rp = Ks + row * KP + half * 32;
        float ss = 0.f;
#pragma unroll
        for (int i = 0; i < 8; i++) {
            float4 x = *(const float4*)(rp + i * 4);
            ss += x.x * x.x + x.y * x.y + x.z * x.z + x.w * x.w;
        }
        ss += __shfl_xor_sync(~0u, ss, 1);
        if (half == 0) nrm[row] = 1.f / fmaxf(sqrtf(ss), 1e-12f);
    }
    __syncthreads();
    uint32_t qf[8][4];
    {
        float inv_lo = nrm[w * 16 + g], inv_hi = nrm[w * 16 + g + 8];
        int rlo = (w * 16 + g) * KP, rhi = (w * 16 + g + 8) * KP;
#pragma unroll
        for (int kc = 0; kc < 8; kc++) {
            int col = kc * 8 + c;
            float s0 = qss[col], s4 = qss[col + 4];
            qf[kc][0] = f2tf(Ks[rlo + col] * inv_lo * s0);
            qf[kc][1] = f2tf(Ks[rhi + col] * inv_hi * s0);
            qf[kc][2] = f2tf(Ks[rlo + col + 4] * inv_lo * s4);
            qf[kc][3] = f2tf(Ks[rhi + col + 4] * inv_hi * s4);
        }
    }
    __syncthreads();

    float m_lo = MASKV, m_hi = MASKV, l_lo = 0.f, l_hi = 0.f;
    float oacc[8][4];
#pragma unroll
    for (int nt = 0; nt < 8; nt++)
#pragma unroll
        for (int i = 0; i < 4; i++) oacc[nt][i] = 0.f;

    const int iq_lo = i0 + w * 16 + g, iq_hi = iq_lo + 8;
    int nPre = qt ? 2 : 1;
    int nTiles = nPre + qt + 1;

    for (int tix = 0; tix < nTiles; tix++) {
        int isPre = (tix < nPre);
        int cbase = isPre ? ((qt ? (qt - 1 + tix) : 0) << 6) : ((tix - nPre) << 6);
        int kvrow0 = (isPre ? 0 : S_P) + cbase;

        const float* kb = k + ((size_t)b * S_J + kvrow0) * 64;
        const float* vb = v + ((size_t)b * S_J + kvrow0) * 64;
        for (int f = t; f < 1024; f += 128) {
            int r = f >> 4, d4 = (f & 15) << 2;
            *(float4*)&Ks[r * KP + d4] = *(const float4*)(kb + r * 64 + d4);
            *(float4*)&Vs[r * VP + d4] = *(const float4*)(vb + r * 64 + d4);
        }
        __syncthreads();

        float sacc[8][4];
#pragma unroll
        for (int nt = 0; nt < 8; nt++)
#pragma unroll
            for (int i = 0; i < 4; i++) sacc[nt][i] = 0.f;
#pragma unroll
        for (int kc = 0; kc < 8; kc++) {
            int col = kc * 8 + c;
#pragma unroll
            for (int nt = 0; nt < 8; nt++) {
                uint32_t bb[2];
                int rb = (nt * 8 + g) * KP;
                bb[0] = __float_as_uint(Ks[rb + col]);
                bb[1] = __float_as_uint(Ks[rb + col + 4]);
                mma8(sacc[nt], qf[kc], bb);
            }
        }
#pragma unroll
        for (int nt = 0; nt < 8; nt++) {
            int jc = cbase + nt * 8 + 2 * c;
            if (isPre) {
                sacc[nt][0] = (iq_lo >= jc     && iq_lo - jc < 16)     ? sacc[nt][0] * 8.f : MASKV;
                sacc[nt][1] = (iq_lo >= jc + 1 && iq_lo - jc - 1 < 16) ? sacc[nt][1] * 8.f : MASKV;
                sacc[nt][2] = (iq_hi >= jc     && iq_hi - jc < 16)     ? sacc[nt][2] * 8.f : MASKV;
                sacc[nt][3] = (iq_hi >= jc + 1 && iq_hi - jc - 1 < 16) ? sacc[nt][3] * 8.f : MASKV;
            } else {
                float2 blo = *(const float2*)(bias + ((size_t)h * S_N + iq_lo) * S_N + jc);
                float2 bhi = *(const float2*)(bias + ((size_t)h * S_N + iq_hi) * S_N + jc);
                sacc[nt][0] = (jc     <= iq_lo) ? sacc[nt][0] * 8.f + blo.x : MASKV;
                sacc[nt][1] = (jc + 1 <= iq_lo) ? sacc[nt][1] * 8.f + blo.y : MASKV;
                sacc[nt][2] = (jc     <= iq_hi) ? sacc[nt][2] * 8.f + bhi.x : MASKV;
                sacc[nt][3] = (jc + 1 <= iq_hi) ? sacc[nt][3] * 8.f + bhi.y : MASKV;
            }
        }
        float mx_lo = MASKV, mx_hi = MASKV;
#pragma unroll
        for (int nt = 0; nt < 8; nt++) {
            mx_lo = fmaxf(mx_lo, fmaxf(sacc[nt][0], sacc[nt][1]));
            mx_hi = fmaxf(mx_hi, fmaxf(sacc[nt][2], sacc[nt][3]));
        }
        mx_lo = fmaxf(mx_lo, __shfl_xor_sync(~0u, mx_lo, 1));
        mx_lo = fmaxf(mx_lo, __shfl_xor_sync(~0u, mx_lo, 2));
        mx_hi = fmaxf(mx_hi, __shfl_xor_sync(~0u, mx_hi, 1));
        mx_hi = fmaxf(mx_hi, __shfl_xor_sync(~0u, mx_hi, 2));
        float mn_lo = fmaxf(m_lo, mx_lo), mn_hi = fmaxf(m_hi, mx_hi);
        float r_lo = __expf(m_lo - mn_lo), r_hi = __expf(m_hi - mn_hi);
        float ps_lo = 0.f, ps_hi = 0.f;
#pragma unroll
        for (int nt = 0; nt < 8; nt++) {
            float p0 = (sacc[nt][0] > -1e29f) ? __expf(sacc[nt][0] - mn_lo) : 0.f;
            float p1 = (sacc[nt][1] > -1e29f) ? __expf(sacc[nt][1] - mn_lo) : 0.f;
            float p2 = (sacc[nt][2] > -1e29f) ? __expf(sacc[nt][2] - mn_hi) : 0.f;
            float p3 = (sacc[nt][3] > -1e29f) ? __expf(sacc[nt][3] - mn_hi) : 0.f;
            ps_lo += p0 + p1; ps_hi += p2 + p3;
            int col = nt * 8 + 2 * c;
            *(float2*)&Pw[g * PQ + col]       = make_float2(f2tf_f(p0), f2tf_f(p1));
            *(float2*)&Pw[(g + 8) * PQ + col] = make_float2(f2tf_f(p2), f2tf_f(p3));
        }
        ps_lo += __shfl_xor_sync(~0u, ps_lo, 1);
        ps_lo += __shfl_xor_sync(~0u, ps_lo, 2);
        ps_hi += __shfl_xor_sync(~0u, ps_hi, 1);
        ps_hi += __shfl_xor_sync(~0u, ps_hi, 2);
        l_lo = l_lo * r_lo + ps_lo; l_hi = l_hi * r_hi + ps_hi;
        m_lo = mn_lo; m_hi = mn_hi;
#pragma unroll
        for (int nt = 0; nt < 8; nt++) {
            oacc[nt][0] *= r_lo; oacc[nt][1] *= r_lo;
            oacc[nt][2] *= r_hi; oacc[nt][3] *= r_hi;
        }
        __syncwarp();
#pragma unroll
        for (int kc = 0; kc < 8; kc++) {
            uint32_t pa[4];
            int col = kc * 8 + c;
            pa[0] = __float_as_uint(Pw[g * PQ + col]);
            pa[1] = __float_as_uint(Pw[(g + 8) * PQ + col]);
            pa[2] = __float_as_uint(Pw[g * PQ + col + 4]);
            pa[3] = __float_as_uint(Pw[(g + 8) * PQ + col + 4]);
#pragma unroll
            for (int nt = 0; nt < 8; nt++) {
                uint32_t bb[2];
                bb[0] = __float_as_uint(Vs[(kc * 8 + c) * VP + nt * 8 + g]);
                bb[1] = __float_as_uint(Vs[(kc * 8 + c + 4) * VP + nt * 8 + g]);
                mma8(oacc[nt], pa, bb);
            }
        }
        __syncthreads();
    }

    float li_lo = 1.f / l_lo, li_hi = 1.f / l_hi;
    float* orow_lo = ao + ((size_t)(b * S_N + iq_lo)) * S_DIM + h * 64;
    float* orow_hi = ao + ((size_t)(b * S_N + iq_hi)) * S_DIM + h * 64;
#pragma unroll
    for (int nt = 0; nt < 8; nt++) {
        int col = nt * 8 + 2 * c;
        *(float2*)(orow_lo + col) = make_float2(f2tf_f(oacc[nt][0] * li_lo), f2tf_f(oacc[nt][1] * li_lo));
        *(float2*)(orow_hi + col) = make_float2(f2tf_f(oacc[nt][2] * li_hi), f2tf_f(oacc[nt][3] * li_hi));
    }
}

// ---------------- launch: batch-pipelined fork/join ------------------------
// s2: KV chain (full).  Stream 0: LN -> Q(b01) -> [fork s3: attn(b01) ->
// O(b01)] -> Q(b23) -> attn(b23) -> O(b23) -> join.
extern "C" void kernel_launch(void* const* d_in, const int* in_sizes, int n_in,
                              void* d_out, int out_size) {
    const float* x      = (const float*)d_in[0];
    const float* prefix = (const float*)d_in[1];
    const float* bias   = (const float*)d_in[2];
    const float* gamma  = (const float*)d_in[3];
    const float* Wq     = (const float*)d_in[4];
    const float* Wkv    = (const float*)d_in[5];
    const float* qscale = (const float*)d_in[6];
    const float* kscale = (const float*)d_in[7];
    const float* Wo     = (const float*)d_in[8];
    float* out = (float*)d_out;

    float *xn, *qraw, *aob, *kvraw, *kk, *vv;
    cudaGetSymbolAddress((void**)&xn,    g_xn);
    cudaGetSymbolAddress((void**)&qraw,  g_qraw);
    cudaGetSymbolAddress((void**)&aob,   g_ao);
    cudaGetSymbolAddress((void**)&kvraw, g_kvr);
    cudaGetSymbolAddress((void**)&kk,    g_k);
    cudaGetSymbolAddress((void**)&vv,    g_v);

    static cudaStream_t s2 = nullptr, s3 = nullptr;
    static cudaEvent_t evRoot = nullptr, evKV = nullptr, evQ01 = nullptr, evO01 = nullptr;
    if (s2 == nullptr) {
        cudaStreamCreateWithFlags(&s2, cudaStreamNonBlocking);
        cudaStreamCreateWithFlags(&s3, cudaStreamNonBlocking);
        cudaEventCreateWithFlags(&evRoot, cudaEventDisableTiming);
        cudaEventCreateWithFlags(&evKV,   cudaEventDisableTiming);
        cudaEventCreateWithFlags(&evQ01,  cudaEventDisableTiming);
        cudaEventCreateWithFlags(&evO01,  cudaEventDisableTiming);
        cudaFuncSetAttribute(mm_tf32<false, true>,  cudaFuncAttributeMaxDynamicSharedMemorySize, MM_SMEM_BYTES);
        cudaFuncSetAttribute(mm_tf32<true,  false>, cudaFuncAttributeMaxDynamicSharedMemorySize, MM_SMEM_BYTES);
        cudaFuncSetAttribute(attn_tc, cudaFuncAttributeMaxDynamicSharedMemorySize, ATTN_SMEM_BYTES);
    }

    const size_t HALF_ROWS = (size_t)2 * S_N;            // 2048 rows
    const size_t HALF_X    = HALF_ROWS * S_DIM;           // xn/qraw/ao/out offset
    const size_t HALF_KV   = (size_t)2 * S_J * 64;        // k/v offset

    // fork KV chain (independent of everything on stream 0)
    cudaEventRecord(evRoot, 0);
    cudaStreamWaitEvent(s2, evRoot, 0);
    mm_tf32<true, false><<<dim3(1, 64), 256, MM_SMEM_BYTES, s2>>>(prefix, x, Wkv, kvraw, S_BJ, 128, S_DIM);
    kvnorm_kernel<<<S_BJ / 8, 256, 0, s2>>>(kvraw, kscale, kk, vv);
    cudaEventRecord(evKV, s2);

    // stream 0: LN (full), then Q projection for batches 0-1
    ln_kernel<<<S_BN, 256>>>(x, gamma, xn);
    mm_tf32<false, true><<<dim3(8, 16), 256, MM_SMEM_BYTES>>>(xn, nullptr, Wq, qraw, 2048, S_DIM, S_DIM);
    cudaEventRecord(evQ01, 0);

    // s3: attention + O projection for batches 0-1 (waits on Q01 and KV)
    cudaStreamWaitEvent(s3, evQ01, 0);
    cudaStreamWaitEvent(s3, evKV, 0);
    attn_tc<<<dim3(16, 32), 128, ATTN_SMEM_BYTES, s3>>>(qraw, kk, vv, bias, qscale, aob);
    mm_tf32<false, true><<<dim3(8, 16), 256, MM_SMEM_BYTES, s3>>>(aob, nullptr, Wo, out, 2048, S_DIM, S_DIM);
    cudaEventRecord(evO01, s3);

    // stream 0: Q projection for batches 2-3 (overlaps attn(b01))
    mm_tf32<false, true><<<dim3(8, 16), 256, MM_SMEM_BYTES>>>(xn + HALF_X, nullptr, Wq, qraw + HALF_X, 2048, S_DIM, S_DIM);
    // attention + O projection for batches 2-3 (overlaps O(b01))
    cudaStreamWaitEvent(0, evKV, 0);
    attn_tc<<<dim3(16, 32), 128, ATTN_SMEM_BYTES>>>(qraw + HALF_X, kk + HALF_KV, vv + HALF_KV, bias, qscale, aob + HALF_X);
    mm_tf32<false, true><<<dim3(8, 16), 256, MM_SMEM_BYTES>>>(aob + HALF_X, nullptr, Wo, out + HALF_X, 2048, S_DIM, S_DIM);

    // join
    cudaStreamWaitEvent(0, evO01, 0);
}